// round 11
// baseline (speedup 1.0000x reference)
#include <cuda_runtime.h>
#include <math.h>
#include <stdint.h>

#define T_C 8192
#define E_C 1024
#define SEG 64
#define SEGL (T_C / SEG)   // 128

// ---------------- scratch (device globals; no allocations allowed) ----------
__device__ float g_kvr[3][T_C * E_C];   // k, v, r
__device__ float g_rwkv[T_C * E_C];
__device__ float g_bt[4 * E_C * E_C];   // transposed weights [N,K] K-major (tf32-rounded)
// segment summaries / initial states
__device__ float g_ua[SEG * E_C];
__device__ float g_ub[SEG * E_C];
__device__ float g_up[SEG * E_C];
__device__ float g_sa[SEG * E_C];
__device__ float g_sb[SEG * E_C];
__device__ float g_sp[SEG * E_C];

// ---------------- PTX helpers (compute_103-portable only) --------------------
__device__ __forceinline__ float tf32r(float x) {
    float y;
    asm("cvt.rna.tf32.f32 %0, %1;" : "=f"(y) : "f"(x));
    return y;
}

__device__ __forceinline__ uint32_t smem_u32(const void* p) {
    uint32_t a;
    asm("{ .reg .u64 t; cvta.to.shared.u64 t, %1; cvt.u32.u64 %0, t; }"
        : "=r"(a) : "l"(p));
    return a;
}

__device__ __forceinline__ void cp16(uint32_t dst, const void* src) {
    asm volatile("cp.async.cg.shared.global [%0], [%1], 16;" :: "r"(dst), "l"(src));
}

__device__ __forceinline__ void ldsm4(uint32_t* r, uint32_t addr) {
    asm volatile("ldmatrix.sync.aligned.m8n8.x4.shared.b16 {%0,%1,%2,%3}, [%4];"
                 : "=r"(r[0]), "=r"(r[1]), "=r"(r[2]), "=r"(r[3]) : "r"(addr));
}

__device__ __forceinline__ void mma_tf32(float* c, const uint32_t* a,
                                         uint32_t b0, uint32_t b1) {
    asm volatile(
        "mma.sync.aligned.m16n8k8.row.col.f32.tf32.tf32.f32 "
        "{%0,%1,%2,%3},{%4,%5,%6,%7},{%8,%9},{%0,%1,%2,%3};"
        : "+f"(c[0]), "+f"(c[1]), "+f"(c[2]), "+f"(c[3])
        : "r"(a[0]), "r"(a[1]), "r"(a[2]), "r"(a[3]), "r"(b0), "r"(b1));
}

#define SWZ(off) ((off) ^ (((off) >> 3) & 0x70))

// ---------------- weight transpose: g_bt[z][n][k] = rna(W_z[k][n]) -----------
__global__ void transpose_kernel(const float* __restrict__ Wk,
                                 const float* __restrict__ Wv,
                                 const float* __restrict__ Wr,
                                 const float* __restrict__ Wo) {
    __shared__ float t[32][33];
    const float* src = (blockIdx.z == 0) ? Wk : (blockIdx.z == 1) ? Wv
                     : (blockIdx.z == 2) ? Wr : Wo;
    float* dst = g_bt + (size_t)blockIdx.z * (E_C * E_C);

    int x  = blockIdx.x * 32 + threadIdx.x;
    int y0 = blockIdx.y * 32;
    #pragma unroll
    for (int j = threadIdx.y; j < 32; j += 8)
        t[j][threadIdx.x] = src[(size_t)(y0 + j) * E_C + x];
    __syncthreads();
    int xo  = blockIdx.y * 32 + threadIdx.x;
    int yo0 = blockIdx.x * 32;
    #pragma unroll
    for (int j = threadIdx.y; j < 32; j += 8)
        dst[(size_t)(yo0 + j) * E_C + xo] = tf32r(t[threadIdx.x][j]);
}

// ---------------- tf32 HMMA GEMM core ----------------------------------------
// 3-stage pipeline, 128x128 CTA tile, 2 CTAs/SM.
#define GSTAGES 3
#define GNITER  32          // K / 32
#define GSMEM_BYTES (GSTAGES * 32768)

// B tile via cp.async (both kernels)
__device__ __forceinline__ void load_stage_B(const float* Bbase, uint32_t stB,
                                             int k0, int tid) {
    #pragma unroll
    for (int i = 0; i < 4; i++) {
        int u = i * 256 + tid;
        int row = u >> 3, c = u & 7;
        uint32_t off = (uint32_t)(row * 128 + c * 16);
        cp16(stB + SWZ(off), Bbase + (size_t)row * E_C + k0 + c * 4);
    }
    asm volatile("cp.async.commit_group;" ::: "memory");
}

// A tile via cp.async (gemm_out)
__device__ __forceinline__ void load_stage_A_cp(const float* Abase, uint32_t stA,
                                                int k0, int tid) {
    #pragma unroll
    for (int i = 0; i < 4; i++) {
        int u = i * 256 + tid;
        int row = u >> 3, c = u & 7;
        uint32_t off = (uint32_t)(row * 128 + c * 16);
        cp16(stA + SWZ(off), Abase + (size_t)row * E_C + k0 + c * 4);
    }
}

// A tile with fused token-shift mix (gemm_kvr): kx = x*m + xprev*(1-m), rna
__device__ __forceinline__ void load_stage_A_mix(const float* __restrict__ x,
                                                 const float* __restrict__ sx,
                                                 const float* __restrict__ tm,
                                                 char* smem_c, uint32_t stage_off,
                                                 int bM, int k0, int tid) {
    #pragma unroll
    for (int i = 0; i < 4; i++) {
        int u = i * 256 + tid;
        int row = u >> 3, c = u & 7;
        int t = bM * 128 + row;
        int k = k0 + c * 4;
        float4 xv = *reinterpret_cast<const float4*>(x + (size_t)t * E_C + k);
        const float* prev = (t == 0) ? (sx + k) : (x + (size_t)(t - 1) * E_C + k);
        float4 pv = *reinterpret_cast<const float4*>(prev);
        float4 mc = *reinterpret_cast<const float4*>(tm + k);
        float4 o;
        o.x = tf32r(xv.x * mc.x + pv.x * (1.f - mc.x));
        o.y = tf32r(xv.y * mc.y + pv.y * (1.f - mc.y));
        o.z = tf32r(xv.z * mc.z + pv.z * (1.f - mc.z));
        o.w = tf32r(xv.w * mc.w + pv.w * (1.f - mc.w));
        uint32_t off = SWZ((uint32_t)(row * 128 + c * 16));
        *reinterpret_cast<float4*>(smem_c + stage_off + off) = o;
    }
}

// shared main body: consumes stages, runs MMAs, writes epilogue.
// LOADER: functor issuing the stage load for k-chunk index ktNext.
template <int MODE, typename LOADER>
__device__ __forceinline__ void gemm_mainloop(LOADER loader,
                                              float* __restrict__ C,
                                              const float* __restrict__ R,
                                              int bN, int bM, uint32_t TILES) {
    const int tid = threadIdx.x;
    const int wid = tid >> 5;
    const int lid = tid & 31;

    const int warp_m = (wid >> 2) * 64;
    const int warp_n = (wid & 3) * 32;
    const int lrow = lid & 7;
    const int g    = lid >> 3;

    float acc[4][4][4];
    #pragma unroll
    for (int mb = 0; mb < 4; mb++)
        #pragma unroll
        for (int nb = 0; nb < 4; nb++)
            #pragma unroll
            for (int q = 0; q < 4; q++) acc[mb][nb][q] = 0.f;

    #pragma unroll
    for (int s = 0; s < GSTAGES - 1; s++) loader(s);

    for (int kt = 0; kt < GNITER; kt++) {
        if (kt >= GNITER - 1)
            asm volatile("cp.async.wait_group 0;" ::: "memory");
        else
            asm volatile("cp.async.wait_group 1;" ::: "memory");
        __syncthreads();

        const uint32_t sA = TILES + (uint32_t)(kt % GSTAGES) * 32768u;
        const uint32_t sB = sA + 16384u;

        #pragma unroll
        for (int ks = 0; ks < 4; ks++) {
            uint32_t af[4][4];
            #pragma unroll
            for (int mb = 0; mb < 4; mb++) {
                int row   = warp_m + mb * 16 + lrow + (g & 1) * 8;
                int chunk = ks * 2 + (g >> 1);
                ldsm4(af[mb], sA + SWZ((uint32_t)(row * 128 + chunk * 16)));
            }
            uint32_t bf[2][4];
            #pragma unroll
            for (int nb2 = 0; nb2 < 2; nb2++) {
                int nrow  = warp_n + nb2 * 16 + lrow + (g >> 1) * 8;
                int chunk = ks * 2 + (g & 1);
                ldsm4(bf[nb2], sB + SWZ((uint32_t)(nrow * 128 + chunk * 16)));
            }
            #pragma unroll
            for (int mb = 0; mb < 4; mb++)
                #pragma unroll
                for (int nb = 0; nb < 4; nb++)
                    mma_tf32(acc[mb][nb], af[mb],
                             bf[nb >> 1][(nb & 1) * 2], bf[nb >> 1][(nb & 1) * 2 + 1]);
        }

        if (kt + GSTAGES - 1 < GNITER) {
            __syncthreads();
            loader(kt + GSTAGES - 1);
        }
    }

    #pragma unroll
    for (int mb = 0; mb < 4; mb++) {
        #pragma unroll
        for (int nb = 0; nb < 4; nb++) {
            const int row0 = bM * 128 + warp_m + mb * 16 + (lid >> 2);
            const int col  = bN * 128 + warp_n + nb * 8 + 2 * (lid & 3);
            #pragma unroll
            for (int h = 0; h < 2; h++) {
                float2 v;
                v.x = acc[mb][nb][h * 2 + 0];
                v.y = acc[mb][nb][h * 2 + 1];
                const size_t idx = (size_t)(row0 + h * 8) * E_C + col;
                if (MODE == 1) {
                    v.x = 1.f / (1.f + __expf(-v.x));
                    v.y = 1.f / (1.f + __expf(-v.y));
                } else if (MODE == 2) {
                    float2 r2 = *reinterpret_cast<const float2*>(R + idx);
                    v.x += r2.x; v.y += r2.y;
                }
                *reinterpret_cast<float2*>(C + idx) = v;
            }
        }
    }
}

// merged k/v/r GEMM with fused token-shift mix on A
__global__ __launch_bounds__(256, 2)
void gemm_kvr_kernel(const float* __restrict__ x,
                     const float* __restrict__ sx,
                     const float* __restrict__ tmk,
                     const float* __restrict__ tmv,
                     const float* __restrict__ tmr) {
    extern __shared__ char smem[];
    const uint32_t TILES = smem_u32(smem);
    const int z  = blockIdx.z;
    const int bN = blockIdx.x, bM = blockIdx.y;
    const float* tm = (z == 0) ? tmk : (z == 1) ? tmv : tmr;
    const float* Bbase = g_bt + (size_t)z * E_C * E_C + (size_t)bN * 128 * E_C;
    const int tid = threadIdx.x;

    auto loader = [&](int ktNext) {
        uint32_t so = (uint32_t)(ktNext % GSTAGES) * 32768u;
        load_stage_A_mix(x, sx, tm, smem, so, bM, ktNext * 32, tid);
        load_stage_B(Bbase, TILES + so + 16384u, ktNext * 32, tid);
    };

    if (z == 2)
        gemm_mainloop<1>(loader, g_kvr[2], nullptr, bN, bM, TILES);
    else if (z == 1)
        gemm_mainloop<0>(loader, g_kvr[1], nullptr, bN, bM, TILES);
    else
        gemm_mainloop<0>(loader, g_kvr[0], nullptr, bN, bM, TILES);
}

// final GEMM: out = x + rwkv @ Wo  (A via cp.async)
__global__ __launch_bounds__(256, 2)
void gemm_out_kernel(float* __restrict__ C, const float* __restrict__ R) {
    extern __shared__ char smem[];
    const uint32_t TILES = smem_u32(smem);
    const int bN = blockIdx.x, bM = blockIdx.y;
    const float* Abase = g_rwkv + (size_t)bM * 128 * E_C;
    const float* Bbase = g_bt + 3 * (size_t)E_C * E_C + (size_t)bN * 128 * E_C;
    const int tid = threadIdx.x;

    auto loader = [&](int ktNext) {
        uint32_t so = (uint32_t)(ktNext % GSTAGES) * 32768u;
        load_stage_A_cp(Abase, TILES + so, ktNext * 32, tid);
        load_stage_B(Bbase, TILES + so + 16384u, ktNext * 32, tid);
    };
    gemm_mainloop<2>(loader, C, R, bN, bM, TILES);
}

// ---------------- Phase A: per-segment zero-init summaries ------------------
__global__ __launch_bounds__(256)
void scanA_kernel(const float* __restrict__ td_in) {
    const int e = blockIdx.x * blockDim.x + threadIdx.x;
    const int s = blockIdx.y;
    const float dec = -__expf(td_in[e]);

    float aa = 0.f, bb = 0.f, pp = -1e30f;
    const size_t base = (size_t)s * SEGL * E_C + e;

    #pragma unroll 1
    for (int j = 0; j < SEGL; j += 8) {
        float kk8[8], vv8[8];
        #pragma unroll
        for (int u = 0; u < 8; u++) {
            kk8[u] = g_kvr[0][base + (size_t)(j + u) * E_C];
            vv8[u] = g_kvr[1][base + (size_t)(j + u) * E_C];
        }
        #pragma unroll
        for (int u = 0; u < 8; u++) {
            const float kk = kk8[u], vv = vv8[u];
            const float ww2 = dec + pp;
            const float d2  = ww2 - kk;
            const float m2  = __expf(-fabsf(d2));
            const float e1b = (d2 >= 0.f) ? 1.f : m2;
            const float e2b = (d2 >= 0.f) ? m2 : 1.f;
            aa = e1b * aa + e2b * vv;
            bb = e1b * bb + e2b;
            pp = (d2 >= 0.f) ? ww2 : kk;
        }
    }
    g_ua[s * E_C + e] = aa;
    g_ub[s * E_C + e] = bb;
    g_up[s * E_C + e] = pp;
}

// ---------------- Phase B: compose summaries --------------------------------
__global__ void scanB_kernel(const float* __restrict__ aa_in,
                             const float* __restrict__ bb_in,
                             const float* __restrict__ pp_in,
                             const float* __restrict__ td_in,
                             const float* __restrict__ x,
                             float* __restrict__ out_tail,
                             int write_tail) {
    const int e = blockIdx.x * blockDim.x + threadIdx.x;
    if (e >= E_C) return;

    float aa = aa_in[e], bb = bb_in[e], pp = pp_in[e];
    const float Ld = (float)SEGL * (-__expf(td_in[e]));

    #pragma unroll 1
    for (int s = 0; s < SEG; s++) {
        g_sa[s * E_C + e] = aa;
        g_sb[s * E_C + e] = bb;
        g_sp[s * E_C + e] = pp;
        const float q  = pp + Ld;
        const float ua = g_ua[s * E_C + e];
        const float ub = g_ub[s * E_C + e];
        const float up = g_up[s * E_C + e];
        const float pn = fmaxf(q, up);
        const float eq = __expf(q - pn);
        const float eu = __expf(up - pn);
        aa = aa * eq + ua * eu;
        bb = bb * eq + ub * eu;
        pp = pn;
    }

    if (write_tail) {
        out_tail[(size_t)T_C * E_C + 0 * E_C + e] = x[(size_t)(T_C - 1) * E_C + e];
        out_tail[(size_t)T_C * E_C + 1 * E_C + e] = aa;
        out_tail[(size_t)T_C * E_C + 2 * E_C + e] = bb;
        out_tail[(size_t)T_C * E_C + 3 * E_C + e] = pp;
    }
}

// ---------------- Phase C: replay segments, emit tf32-rounded r*wkv ---------
__global__ __launch_bounds__(256)
void scanC_kernel(const float* __restrict__ tf_in,
                  const float* __restrict__ td_in) {
    const int e = blockIdx.x * blockDim.x + threadIdx.x;
    const int s = blockIdx.y;
    const float tf  = tf_in[e];
    const float dec = -__expf(td_in[e]);

    float aa = g_sa[s * E_C + e];
    float bb = g_sb[s * E_C + e];
    float pp = g_sp[s * E_C + e];
    const size_t base = (size_t)s * SEGL * E_C + e;

    #pragma unroll 1
    for (int j = 0; j < SEGL; j += 8) {
        float kk8[8], vv8[8], rr8[8];
        #pragma unroll
        for (int u = 0; u < 8; u++) {
            kk8[u] = g_kvr[0][base + (size_t)(j + u) * E_C];
            vv8[u] = g_kvr[1][base + (size_t)(j + u) * E_C];
            rr8[u] = g_kvr[2][base + (size_t)(j + u) * E_C];
        }
        float out8[8];
        #pragma unroll
        for (int u = 0; u < 8; u++) {
            const float kk = kk8[u], vv = vv8[u];

            const float ww = tf + kk;
            const float d  = pp - ww;
            const float m  = __expf(-fabsf(d));
            const float e1 = (d >= 0.f) ? 1.f : m;
            const float e2 = (d >= 0.f) ? m : 1.f;
            out8[u] = tf32r(rr8[u] * __fdividef(e1 * aa + e2 * vv, e1 * bb + e2));

            const float ww2 = dec + pp;
            const float d2  = ww2 - kk;
            const float m2  = __expf(-fabsf(d2));
            const float e1b = (d2 >= 0.f) ? 1.f : m2;
            const float e2b = (d2 >= 0.f) ? m2 : 1.f;
            aa = e1b * aa + e2b * vv;
            bb = e1b * bb + e2b;
            pp = (d2 >= 0.f) ? ww2 : kk;
        }
        #pragma unroll
        for (int u = 0; u < 8; u++)
            g_rwkv[base + (size_t)(j + u) * E_C] = out8[u];
    }
}

// ---------------- launch -----------------------------------------------------
extern "C" void kernel_launch(void* const* d_in, const int* in_sizes, int n_in,
                              void* d_out, int out_size) {
    const float* x   = (const float*)d_in[0];
    const float* sx  = (const float*)d_in[1];
    const float* aa  = (const float*)d_in[2];
    const float* bb  = (const float*)d_in[3];
    const float* pp  = (const float*)d_in[4];
    const float* tf  = (const float*)d_in[5];
    const float* td  = (const float*)d_in[6];
    const float* tmk = (const float*)d_in[7];
    const float* tmv = (const float*)d_in[8];
    const float* tmr = (const float*)d_in[9];
    const float* Wk  = (const float*)d_in[10];
    const float* Wv  = (const float*)d_in[11];
    const float* Wr  = (const float*)d_in[12];
    const float* Wo  = (const float*)d_in[13];
    float* out = (float*)d_out;

    cudaFuncSetAttribute(gemm_kvr_kernel,
                         cudaFuncAttributeMaxDynamicSharedMemorySize, GSMEM_BYTES);
    cudaFuncSetAttribute(gemm_out_kernel,
                         cudaFuncAttributeMaxDynamicSharedMemorySize, GSMEM_BYTES);

    // 1) weight transposes -> [N,K] K-major, tf32-rounded
    transpose_kernel<<<dim3(32, 32, 4), dim3(32, 8)>>>(Wk, Wv, Wr, Wo);

    // 2) merged k, v, r GEMMs with fused token-shift mix (HMMA tf32)
    gemm_kvr_kernel<<<dim3(E_C / 128, T_C / 128, 3), 256, GSMEM_BYTES>>>(
        x, sx, tmk, tmv, tmr);

    // 3) segment-parallel WKV scan
    const int write_tail = (out_size >= T_C * E_C + 4 * E_C) ? 1 : 0;
    dim3 sgrid(E_C / 256, SEG);
    scanA_kernel<<<sgrid, 256>>>(td);
    scanB_kernel<<<4, 256>>>(aa, bb, pp, td, x, out, write_tail);
    scanC_kernel<<<sgrid, 256>>>(tf, td);

    // 4) out = x + rwkv @ Wo
    gemm_out_kernel<<<dim3(E_C / 128, T_C / 128), 256, GSMEM_BYTES>>>(out, x);
}

// round 13
// speedup vs baseline: 1.2001x; 1.2001x over previous
#include <cuda_runtime.h>
#include <math.h>
#include <stdint.h>

#define T_C 8192
#define E_C 1024
#define SEG 64
#define SEGL (T_C / SEG)   // 128

// ---------------- scratch (device globals; no allocations allowed) ----------
__device__ float g_mix[3][T_C * E_C];   // kx, vx, rx
__device__ float g_kvr[3][T_C * E_C];   // k, v, r
__device__ float g_rwkv[T_C * E_C];
__device__ float g_bt[4 * E_C * E_C];   // transposed weights [N,K] K-major (tf32-rounded)
// segment summaries / initial states
__device__ float g_ua[SEG * E_C];
__device__ float g_ub[SEG * E_C];
__device__ float g_up[SEG * E_C];
__device__ float g_sa[SEG * E_C];
__device__ float g_sb[SEG * E_C];
__device__ float g_sp[SEG * E_C];

// ---------------- PTX helpers (compute_103-portable only) --------------------
__device__ __forceinline__ float tf32r(float x) {
    float y;
    asm("cvt.rna.tf32.f32 %0, %1;" : "=f"(y) : "f"(x));
    return y;
}

__device__ __forceinline__ uint32_t smem_u32(const void* p) {
    uint32_t a;
    asm("{ .reg .u64 t; cvta.to.shared.u64 t, %1; cvt.u32.u64 %0, t; }"
        : "=r"(a) : "l"(p));
    return a;
}

__device__ __forceinline__ void cp16(uint32_t dst, const void* src) {
    asm volatile("cp.async.cg.shared.global [%0], [%1], 16;" :: "r"(dst), "l"(src));
}

__device__ __forceinline__ void ldsm4(uint32_t* r, uint32_t addr) {
    asm volatile("ldmatrix.sync.aligned.m8n8.x4.shared.b16 {%0,%1,%2,%3}, [%4];"
                 : "=r"(r[0]), "=r"(r[1]), "=r"(r[2]), "=r"(r[3]) : "r"(addr));
}

__device__ __forceinline__ void mma_tf32(float* c, const uint32_t* a,
                                         uint32_t b0, uint32_t b1) {
    asm volatile(
        "mma.sync.aligned.m16n8k8.row.col.f32.tf32.tf32.f32 "
        "{%0,%1,%2,%3},{%4,%5,%6,%7},{%8,%9},{%0,%1,%2,%3};"
        : "+f"(c[0]), "+f"(c[1]), "+f"(c[2]), "+f"(c[3])
        : "r"(a[0]), "r"(a[1]), "r"(a[2]), "r"(a[3]), "r"(b0), "r"(b1));
}

#define SWZ(off) ((off) ^ (((off) >> 3) & 0x70))

// ---------------- token-shift mix (tf32-rounded outputs) ---------------------
__global__ void mix_kernel(const float* __restrict__ x,
                           const float* __restrict__ sx,
                           const float* __restrict__ tmk,
                           const float* __restrict__ tmv,
                           const float* __restrict__ tmr) {
    int idx = blockIdx.x * blockDim.x + threadIdx.x;
    const int n4 = T_C * E_C / 4;
    if (idx >= n4) return;
    const int E4 = E_C / 4;
    int e4 = idx % E4;
    int t  = idx / E4;

    float4 xv = reinterpret_cast<const float4*>(x)[idx];
    float4 sv = (t == 0) ? reinterpret_cast<const float4*>(sx)[e4]
                         : reinterpret_cast<const float4*>(x)[idx - E4];
    float4 mk = reinterpret_cast<const float4*>(tmk)[e4];
    float4 mv = reinterpret_cast<const float4*>(tmv)[e4];
    float4 mr = reinterpret_cast<const float4*>(tmr)[e4];

    float4 o;
    o.x = tf32r(xv.x * mk.x + sv.x * (1.f - mk.x));
    o.y = tf32r(xv.y * mk.y + sv.y * (1.f - mk.y));
    o.z = tf32r(xv.z * mk.z + sv.z * (1.f - mk.z));
    o.w = tf32r(xv.w * mk.w + sv.w * (1.f - mk.w));
    reinterpret_cast<float4*>(g_mix[0])[idx] = o;

    o.x = tf32r(xv.x * mv.x + sv.x * (1.f - mv.x));
    o.y = tf32r(xv.y * mv.y + sv.y * (1.f - mv.y));
    o.z = tf32r(xv.z * mv.z + sv.z * (1.f - mv.z));
    o.w = tf32r(xv.w * mv.w + sv.w * (1.f - mv.w));
    reinterpret_cast<float4*>(g_mix[1])[idx] = o;

    o.x = tf32r(xv.x * mr.x + sv.x * (1.f - mr.x));
    o.y = tf32r(xv.y * mr.y + sv.y * (1.f - mr.y));
    o.z = tf32r(xv.z * mr.z + sv.z * (1.f - mr.z));
    o.w = tf32r(xv.w * mr.w + sv.w * (1.f - mr.w));
    reinterpret_cast<float4*>(g_mix[2])[idx] = o;
}

// ---------------- weight transpose: g_bt[z][n][k] = rna(W_z[k][n]) -----------
__global__ void transpose_kernel(const float* __restrict__ Wk,
                                 const float* __restrict__ Wv,
                                 const float* __restrict__ Wr,
                                 const float* __restrict__ Wo) {
    __shared__ float t[32][33];
    const float* src = (blockIdx.z == 0) ? Wk : (blockIdx.z == 1) ? Wv
                     : (blockIdx.z == 2) ? Wr : Wo;
    float* dst = g_bt + (size_t)blockIdx.z * (E_C * E_C);

    int x  = blockIdx.x * 32 + threadIdx.x;
    int y0 = blockIdx.y * 32;
    #pragma unroll
    for (int j = threadIdx.y; j < 32; j += 8)
        t[j][threadIdx.x] = src[(size_t)(y0 + j) * E_C + x];
    __syncthreads();
    int xo  = blockIdx.y * 32 + threadIdx.x;
    int yo0 = blockIdx.x * 32;
    #pragma unroll
    for (int j = threadIdx.y; j < 32; j += 8)
        dst[(size_t)(yo0 + j) * E_C + xo] = tf32r(t[threadIdx.x][j]);
}

// ---------------- tf32 HMMA GEMM core ----------------------------------------
// 3-stage cp.async pipeline, 128x128 CTA tile, 2 CTAs/SM.
#define GSTAGES 3
#define GNITER  32          // K / 32
#define GSMEM_BYTES (GSTAGES * 32768)

__device__ __forceinline__ void gemm_load_stage(const float* Abase, const float* Bbase,
                                                uint32_t stA, int k0, int tid) {
    #pragma unroll
    for (int i = 0; i < 4; i++) {
        int u = i * 256 + tid;
        int row = u >> 3, c = u & 7;
        uint32_t off = (uint32_t)(row * 128 + c * 16);
        cp16(stA + SWZ(off), Abase + (size_t)row * E_C + k0 + c * 4);
    }
    uint32_t stB = stA + 16384u;
    #pragma unroll
    for (int i = 0; i < 4; i++) {
        int u = i * 256 + tid;
        int row = u >> 3, c = u & 7;
        uint32_t off = (uint32_t)(row * 128 + c * 16);
        cp16(stB + SWZ(off), Bbase + (size_t)row * E_C + k0 + c * 4);
    }
    asm volatile("cp.async.commit_group;" ::: "memory");
}

// body shared by both GEMM kernels; mode: 0 plain, 1 sigmoid, 2 residual
__device__ __forceinline__ void gemm_body(const float* __restrict__ A,
                                          const float* __restrict__ Bt,
                                          float* __restrict__ C,
                                          const float* __restrict__ R,
                                          int mode, int bN, int bM) {
    extern __shared__ char smem[];
    const uint32_t TILES = smem_u32(smem);
    const int tid = threadIdx.x;
    const int wid = tid >> 5;
    const int lid = tid & 31;

    const int warp_m = (wid >> 2) * 64;
    const int warp_n = (wid & 3) * 32;

    const int lrow = lid & 7;
    const int g    = lid >> 3;

    const float* Abase = A  + (size_t)bM * 128 * E_C;
    const float* Bbase = Bt + (size_t)bN * 128 * E_C;

    float acc[4][4][4];
    #pragma unroll
    for (int mb = 0; mb < 4; mb++)
        #pragma unroll
        for (int nb = 0; nb < 4; nb++)
            #pragma unroll
            for (int q = 0; q < 4; q++) acc[mb][nb][q] = 0.f;

    #pragma unroll
    for (int s = 0; s < GSTAGES - 1; s++)
        gemm_load_stage(Abase, Bbase, TILES + (uint32_t)s * 32768u, s * 32, tid);

    for (int kt = 0; kt < GNITER; kt++) {
        if (kt >= GNITER - 1)
            asm volatile("cp.async.wait_group 0;" ::: "memory");
        else
            asm volatile("cp.async.wait_group 1;" ::: "memory");
        __syncthreads();

        const uint32_t sA = TILES + (uint32_t)(kt % GSTAGES) * 32768u;
        const uint32_t sB = sA + 16384u;

        #pragma unroll
        for (int ks = 0; ks < 4; ks++) {
            uint32_t af[4][4];
            #pragma unroll
            for (int mb = 0; mb < 4; mb++) {
                int row   = warp_m + mb * 16 + lrow + (g & 1) * 8;
                int chunk = ks * 2 + (g >> 1);
                ldsm4(af[mb], sA + SWZ((uint32_t)(row * 128 + chunk * 16)));
            }
            uint32_t bf[2][4];
            #pragma unroll
            for (int nb2 = 0; nb2 < 2; nb2++) {
                int nrow  = warp_n + nb2 * 16 + lrow + (g >> 1) * 8;
                int chunk = ks * 2 + (g & 1);
                ldsm4(bf[nb2], sB + SWZ((uint32_t)(nrow * 128 + chunk * 16)));
            }
            #pragma unroll
            for (int mb = 0; mb < 4; mb++)
                #pragma unroll
                for (int nb = 0; nb < 4; nb++)
                    mma_tf32(acc[mb][nb], af[mb],
                             bf[nb >> 1][(nb & 1) * 2], bf[nb >> 1][(nb & 1) * 2 + 1]);
        }

        if (kt + GSTAGES - 1 < GNITER) {
            __syncthreads();
            gemm_load_stage(Abase, Bbase,
                            TILES + (uint32_t)((kt + GSTAGES - 1) % GSTAGES) * 32768u,
                            (kt + GSTAGES - 1) * 32, tid);
        }
    }

    #pragma unroll
    for (int mb = 0; mb < 4; mb++) {
        #pragma unroll
        for (int nb = 0; nb < 4; nb++) {
            const int row0 = bM * 128 + warp_m + mb * 16 + (lid >> 2);
            const int col  = bN * 128 + warp_n + nb * 8 + 2 * (lid & 3);
            #pragma unroll
            for (int h = 0; h < 2; h++) {
                float2 v;
                v.x = acc[mb][nb][h * 2 + 0];
                v.y = acc[mb][nb][h * 2 + 1];
                const size_t idx = (size_t)(row0 + h * 8) * E_C + col;
                if (mode == 1) {
                    v.x = 1.f / (1.f + __expf(-v.x));
                    v.y = 1.f / (1.f + __expf(-v.y));
                } else if (mode == 2) {
                    float2 r2 = *reinterpret_cast<const float2*>(R + idx);
                    v.x += r2.x; v.y += r2.y;
                }
                *reinterpret_cast<float2*>(C + idx) = v;
            }
        }
    }
}

// merged k/v/r GEMM: blockIdx.z selects slice; z==2 applies sigmoid
__global__ __launch_bounds__(256, 2)
void gemm_kvr_kernel() {
    const int z = blockIdx.z;
    gemm_body(g_mix[z], g_bt + (size_t)z * E_C * E_C, g_kvr[z], nullptr,
              (z == 2) ? 1 : 0, blockIdx.x, blockIdx.y);
}

// final GEMM: out = x + rwkv @ Wo
__global__ __launch_bounds__(256, 2)
void gemm_out_kernel(float* __restrict__ C, const float* __restrict__ R) {
    gemm_body(g_rwkv, g_bt + 3 * (size_t)E_C * E_C, C, R, 2, blockIdx.x, blockIdx.y);
}

// ---------------- Phase A: per-segment zero-init summaries ------------------
// double-buffered 8-step chunks: prefetch chunk c+1 while computing chunk c
__global__ __launch_bounds__(256)
void scanA_kernel(const float* __restrict__ td_in) {
    const int e = blockIdx.x * blockDim.x + threadIdx.x;
    const int s = blockIdx.y;
    const float dec = -__expf(td_in[e]);

    float aa = 0.f, bb = 0.f, pp = -1e30f;
    const size_t base = (size_t)s * SEGL * E_C + e;
    constexpr int NC = SEGL / 8;     // 16 chunks

    float kb[2][8], vb[2][8];
    #pragma unroll
    for (int u = 0; u < 8; u++) {
        kb[0][u] = g_kvr[0][base + (size_t)u * E_C];
        vb[0][u] = g_kvr[1][base + (size_t)u * E_C];
    }

    #pragma unroll 1
    for (int c = 0; c < NC; c++) {
        const int cur = c & 1;
        if (c + 1 < NC) {
            const size_t nb = base + (size_t)(c + 1) * 8 * E_C;
            #pragma unroll
            for (int u = 0; u < 8; u++) {
                kb[cur ^ 1][u] = g_kvr[0][nb + (size_t)u * E_C];
                vb[cur ^ 1][u] = g_kvr[1][nb + (size_t)u * E_C];
            }
        }
        #pragma unroll
        for (int u = 0; u < 8; u++) {
            const float kk = kb[cur][u], vv = vb[cur][u];
            const float ww2 = dec + pp;
            const float d2  = ww2 - kk;
            const float m2  = __expf(-fabsf(d2));
            const float e1b = (d2 >= 0.f) ? 1.f : m2;
            const float e2b = (d2 >= 0.f) ? m2 : 1.f;
            aa = e1b * aa + e2b * vv;
            bb = e1b * bb + e2b;
            pp = (d2 >= 0.f) ? ww2 : kk;
        }
    }
    g_ua[s * E_C + e] = aa;
    g_ub[s * E_C + e] = bb;
    g_up[s * E_C + e] = pp;
}

// ---------------- Phase B: compose summaries (prefetched) --------------------
__global__ void scanB_kernel(const float* __restrict__ aa_in,
                             const float* __restrict__ bb_in,
                             const float* __restrict__ pp_in,
                             const float* __restrict__ td_in,
                             const float* __restrict__ x,
                             float* __restrict__ out_tail,
                             int write_tail) {
    const int e = blockIdx.x * blockDim.x + threadIdx.x;
    if (e >= E_C) return;

    float aa = aa_in[e], bb = bb_in[e], pp = pp_in[e];
    const float Ld = (float)SEGL * (-__expf(td_in[e]));
    constexpr int NB = SEG / 8;      // 8 batches

    float ua[2][8], ub[2][8], up[2][8];
    #pragma unroll
    for (int u = 0; u < 8; u++) {
        ua[0][u] = g_ua[u * E_C + e];
        ub[0][u] = g_ub[u * E_C + e];
        up[0][u] = g_up[u * E_C + e];
    }

    #pragma unroll 1
    for (int c = 0; c < NB; c++) {
        const int cur = c & 1;
        if (c + 1 < NB) {
            const int nb = (c + 1) * 8;
            #pragma unroll
            for (int u = 0; u < 8; u++) {
                ua[cur ^ 1][u] = g_ua[(nb + u) * E_C + e];
                ub[cur ^ 1][u] = g_ub[(nb + u) * E_C + e];
                up[cur ^ 1][u] = g_up[(nb + u) * E_C + e];
            }
        }
        #pragma unroll
        for (int u = 0; u < 8; u++) {
            const int s = c * 8 + u;
            g_sa[s * E_C + e] = aa;
            g_sb[s * E_C + e] = bb;
            g_sp[s * E_C + e] = pp;
            const float q  = pp + Ld;
            const float pn = fmaxf(q, up[cur][u]);
            const float eq = __expf(q - pn);
            const float eu = __expf(up[cur][u] - pn);
            aa = aa * eq + ua[cur][u] * eu;
            bb = bb * eq + ub[cur][u] * eu;
            pp = pn;
        }
    }

    if (write_tail) {
        out_tail[(size_t)T_C * E_C + 0 * E_C + e] = x[(size_t)(T_C - 1) * E_C + e];
        out_tail[(size_t)T_C * E_C + 1 * E_C + e] = aa;
        out_tail[(size_t)T_C * E_C + 2 * E_C + e] = bb;
        out_tail[(size_t)T_C * E_C + 3 * E_C + e] = pp;
    }
}

// ---------------- Phase C: replay segments (double-buffered) -----------------
__global__ __launch_bounds__(256)
void scanC_kernel(const float* __restrict__ tf_in,
                  const float* __restrict__ td_in) {
    const int e = blockIdx.x * blockDim.x + threadIdx.x;
    const int s = blockIdx.y;
    const float tf  = tf_in[e];
    const float dec = -__expf(td_in[e]);

    float aa = g_sa[s * E_C + e];
    float bb = g_sb[s * E_C + e];
    float pp = g_sp[s * E_C + e];
    const size_t base = (size_t)s * SEGL * E_C + e;
    constexpr int NC = SEGL / 8;     // 16 chunks

    float kb[2][8], vb[2][8], rb[2][8];
    #pragma unroll
    for (int u = 0; u < 8; u++) {
        kb[0][u] = g_kvr[0][base + (size_t)u * E_C];
        vb[0][u] = g_kvr[1][base + (size_t)u * E_C];
        rb[0][u] = g_kvr[2][base + (size_t)u * E_C];
    }

    #pragma unroll 1
    for (int c = 0; c < NC; c++) {
        const int cur = c & 1;
        if (c + 1 < NC) {
            const size_t nb = base + (size_t)(c + 1) * 8 * E_C;
            #pragma unroll
            for (int u = 0; u < 8; u++) {
                kb[cur ^ 1][u] = g_kvr[0][nb + (size_t)u * E_C];
                vb[cur ^ 1][u] = g_kvr[1][nb + (size_t)u * E_C];
                rb[cur ^ 1][u] = g_kvr[2][nb + (size_t)u * E_C];
            }
        }
        float out8[8];
        #pragma unroll
        for (int u = 0; u < 8; u++) {
            const float kk = kb[cur][u], vv = vb[cur][u];

            const float ww = tf + kk;
            const float d  = pp - ww;
            const float m  = __expf(-fabsf(d));
            const float e1 = (d >= 0.f) ? 1.f : m;
            const float e2 = (d >= 0.f) ? m : 1.f;
            out8[u] = tf32r(rb[cur][u] * __fdividef(e1 * aa + e2 * vv, e1 * bb + e2));

            const float ww2 = dec + pp;
            const float d2  = ww2 - kk;
            const float m2  = __expf(-fabsf(d2));
            const float e1b = (d2 >= 0.f) ? 1.f : m2;
            const float e2b = (d2 >= 0.f) ? m2 : 1.f;
            aa = e1b * aa + e2b * vv;
            bb = e1b * bb + e2b;
            pp = (d2 >= 0.f) ? ww2 : kk;
        }
        const size_t ob = base + (size_t)c * 8 * E_C;
        #pragma unroll
        for (int u = 0; u < 8; u++)
            g_rwkv[ob + (size_t)u * E_C] = out8[u];
    }
}

// ---------------- launch -----------------------------------------------------
extern "C" void kernel_launch(void* const* d_in, const int* in_sizes, int n_in,
                              void* d_out, int out_size) {
    const float* x   = (const float*)d_in[0];
    const float* sx  = (const float*)d_in[1];
    const float* aa  = (const float*)d_in[2];
    const float* bb  = (const float*)d_in[3];
    const float* pp  = (const float*)d_in[4];
    const float* tf  = (const float*)d_in[5];
    const float* td  = (const float*)d_in[6];
    const float* tmk = (const float*)d_in[7];
    const float* tmv = (const float*)d_in[8];
    const float* tmr = (const float*)d_in[9];
    const float* Wk  = (const float*)d_in[10];
    const float* Wv  = (const float*)d_in[11];
    const float* Wr  = (const float*)d_in[12];
    const float* Wo  = (const float*)d_in[13];
    float* out = (float*)d_out;

    cudaFuncSetAttribute(gemm_kvr_kernel,
                         cudaFuncAttributeMaxDynamicSharedMemorySize, GSMEM_BYTES);
    cudaFuncSetAttribute(gemm_out_kernel,
                         cudaFuncAttributeMaxDynamicSharedMemorySize, GSMEM_BYTES);

    // 1) token-shift mixes (tf32-rounded)
    {
        const int n4 = T_C * E_C / 4;
        mix_kernel<<<(n4 + 255) / 256, 256>>>(x, sx, tmk, tmv, tmr);
    }

    // 2) weight transposes -> [N,K] K-major, tf32-rounded
    transpose_kernel<<<dim3(32, 32, 4), dim3(32, 8)>>>(Wk, Wv, Wr, Wo);

    // 3) merged k, v, r GEMMs (HMMA tf32)
    gemm_kvr_kernel<<<dim3(E_C / 128, T_C / 128, 3), 256, GSMEM_BYTES>>>();

    // 4) segment-parallel WKV scan
    const int write_tail = (out_size >= T_C * E_C + 4 * E_C) ? 1 : 0;
    dim3 sgrid(E_C / 256, SEG);
    scanA_kernel<<<sgrid, 256>>>(td);
    scanB_kernel<<<4, 256>>>(aa, bb, pp, td, x, out, write_tail);
    scanC_kernel<<<sgrid, 256>>>(tf, td);

    // 5) out = x + rwkv @ Wo
    gemm_out_kernel<<<dim3(E_C / 128, T_C / 128), 256, GSMEM_BYTES>>>(out, x);
}

// round 16
// speedup vs baseline: 1.3049x; 1.0873x over previous
#include <cuda_runtime.h>
#include <math.h>
#include <stdint.h>

#define T_C 8192
#define E_C 1024
#define SEG 128
#define SEGL (T_C / SEG)   // 64

// ---------------- scratch (device globals; no allocations allowed) ----------
__device__ float g_mix[3][T_C * E_C];   // kx, vx, rx
__device__ float g_kvr[3][T_C * E_C];   // k, v, r
__device__ float g_rwkv[T_C * E_C];
__device__ float g_bt[4 * E_C * E_C];   // transposed weights [N,K] K-major (tf32-rounded)
// segment summaries / initial states
__device__ float g_ua[SEG * E_C];
__device__ float g_ub[SEG * E_C];
__device__ float g_up[SEG * E_C];
__device__ float g_sa[SEG * E_C];
__device__ float g_sb[SEG * E_C];
__device__ float g_sp[SEG * E_C];

// ---------------- PTX helpers (compute_103-portable only) --------------------
__device__ __forceinline__ float tf32r(float x) {
    float y;
    asm("cvt.rna.tf32.f32 %0, %1;" : "=f"(y) : "f"(x));
    return y;
}

__device__ __forceinline__ uint32_t smem_u32(const void* p) {
    uint32_t a;
    asm("{ .reg .u64 t; cvta.to.shared.u64 t, %1; cvt.u32.u64 %0, t; }"
        : "=r"(a) : "l"(p));
    return a;
}

__device__ __forceinline__ void cp16(uint32_t dst, const void* src) {
    asm volatile("cp.async.cg.shared.global [%0], [%1], 16;" :: "r"(dst), "l"(src));
}

__device__ __forceinline__ void ldsm4(uint32_t* r, uint32_t addr) {
    asm volatile("ldmatrix.sync.aligned.m8n8.x4.shared.b16 {%0,%1,%2,%3}, [%4];"
                 : "=r"(r[0]), "=r"(r[1]), "=r"(r[2]), "=r"(r[3]) : "r"(addr));
}

__device__ __forceinline__ void mma_tf32(float* c, const uint32_t* a,
                                         uint32_t b0, uint32_t b1) {
    asm volatile(
        "mma.sync.aligned.m16n8k8.row.col.f32.tf32.tf32.f32 "
        "{%0,%1,%2,%3},{%4,%5,%6,%7},{%8,%9},{%0,%1,%2,%3};"
        : "+f"(c[0]), "+f"(c[1]), "+f"(c[2]), "+f"(c[3])
        : "r"(a[0]), "r"(a[1]), "r"(a[2]), "r"(a[3]), "r"(b0), "r"(b1));
}

#define SWZ(off) ((off) ^ (((off) >> 3) & 0x70))

// wkv inner steps ------------------------------------------------------------
__device__ __forceinline__ void wkv_update(float kk, float vv, float dec,
                                           float& aa, float& bb, float& pp) {
    const float ww2 = dec + pp;
    const float d2  = ww2 - kk;
    const float m2  = __expf(-fabsf(d2));
    const float e1b = (d2 >= 0.f) ? 1.f : m2;
    const float e2b = (d2 >= 0.f) ? m2 : 1.f;
    aa = e1b * aa + e2b * vv;
    bb = e1b * bb + e2b;
    pp = (d2 >= 0.f) ? ww2 : kk;
}

__device__ __forceinline__ float wkv_out(float kk, float vv, float rr, float tf,
                                         float aa, float bb, float pp) {
    const float ww = tf + kk;
    const float d  = pp - ww;
    const float m  = __expf(-fabsf(d));
    const float e1 = (d >= 0.f) ? 1.f : m;
    const float e2 = (d >= 0.f) ? m : 1.f;
    return tf32r(rr * __fdividef(e1 * aa + e2 * vv, e1 * bb + e2));
}

// ---------------- token-shift mix (tf32-rounded outputs) ---------------------
__global__ void mix_kernel(const float* __restrict__ x,
                           const float* __restrict__ sx,
                           const float* __restrict__ tmk,
                           const float* __restrict__ tmv,
                           const float* __restrict__ tmr) {
    int idx = blockIdx.x * blockDim.x + threadIdx.x;
    const int n4 = T_C * E_C / 4;
    if (idx >= n4) return;
    const int E4 = E_C / 4;
    int e4 = idx % E4;
    int t  = idx / E4;

    float4 xv = reinterpret_cast<const float4*>(x)[idx];
    float4 sv = (t == 0) ? reinterpret_cast<const float4*>(sx)[e4]
                         : reinterpret_cast<const float4*>(x)[idx - E4];
    float4 mk = reinterpret_cast<const float4*>(tmk)[e4];
    float4 mv = reinterpret_cast<const float4*>(tmv)[e4];
    float4 mr = reinterpret_cast<const float4*>(tmr)[e4];

    float4 o;
    o.x = tf32r(xv.x * mk.x + sv.x * (1.f - mk.x));
    o.y = tf32r(xv.y * mk.y + sv.y * (1.f - mk.y));
    o.z = tf32r(xv.z * mk.z + sv.z * (1.f - mk.z));
    o.w = tf32r(xv.w * mk.w + sv.w * (1.f - mk.w));
    reinterpret_cast<float4*>(g_mix[0])[idx] = o;

    o.x = tf32r(xv.x * mv.x + sv.x * (1.f - mv.x));
    o.y = tf32r(xv.y * mv.y + sv.y * (1.f - mv.y));
    o.z = tf32r(xv.z * mv.z + sv.z * (1.f - mv.z));
    o.w = tf32r(xv.w * mv.w + sv.w * (1.f - mv.w));
    reinterpret_cast<float4*>(g_mix[1])[idx] = o;

    o.x = tf32r(xv.x * mr.x + sv.x * (1.f - mr.x));
    o.y = tf32r(xv.y * mr.y + sv.y * (1.f - mr.y));
    o.z = tf32r(xv.z * mr.z + sv.z * (1.f - mr.z));
    o.w = tf32r(xv.w * mr.w + sv.w * (1.f - mr.w));
    reinterpret_cast<float4*>(g_mix[2])[idx] = o;
}

// ---------------- weight transpose: g_bt[z][n][k] = rna(W_z[k][n]) -----------
__global__ void transpose_kernel(const float* __restrict__ Wk,
                                 const float* __restrict__ Wv,
                                 const float* __restrict__ Wr,
                                 const float* __restrict__ Wo) {
    __shared__ float t[32][33];
    const float* src = (blockIdx.z == 0) ? Wk : (blockIdx.z == 1) ? Wv
                     : (blockIdx.z == 2) ? Wr : Wo;
    float* dst = g_bt + (size_t)blockIdx.z * (E_C * E_C);

    int x  = blockIdx.x * 32 + threadIdx.x;
    int y0 = blockIdx.y * 32;
    #pragma unroll
    for (int j = threadIdx.y; j < 32; j += 8)
        t[j][threadIdx.x] = src[(size_t)(y0 + j) * E_C + x];
    __syncthreads();
    int xo  = blockIdx.y * 32 + threadIdx.x;
    int yo0 = blockIdx.x * 32;
    #pragma unroll
    for (int j = threadIdx.y; j < 32; j += 8)
        dst[(size_t)(yo0 + j) * E_C + xo] = tf32r(t[threadIdx.x][j]);
}

// ---------------- tf32 HMMA GEMM core ----------------------------------------
// 3-stage cp.async pipeline, 128x128 CTA tile, 2 CTAs/SM.
#define GSTAGES 3
#define GNITER  32          // K / 32
#define GSMEM_BYTES (GSTAGES * 32768)

__device__ __forceinline__ void gemm_load_stage(const float* Abase, const float* Bbase,
                                                uint32_t stA, int k0, int tid) {
    #pragma unroll
    for (int i = 0; i < 4; i++) {
        int u = i * 256 + tid;
        int row = u >> 3, c = u & 7;
        uint32_t off = (uint32_t)(row * 128 + c * 16);
        cp16(stA + SWZ(off), Abase + (size_t)row * E_C + k0 + c * 4);
    }
    uint32_t stB = stA + 16384u;
    #pragma unroll
    for (int i = 0; i < 4; i++) {
        int u = i * 256 + tid;
        int row = u >> 3, c = u & 7;
        uint32_t off = (uint32_t)(row * 128 + c * 16);
        cp16(stB + SWZ(off), Bbase + (size_t)row * E_C + k0 + c * 4);
    }
    asm volatile("cp.async.commit_group;" ::: "memory");
}

// body shared by both GEMM kernels; mode: 0 plain, 1 sigmoid, 2 residual
__device__ __forceinline__ void gemm_body(const float* __restrict__ A,
                                          const float* __restrict__ Bt,
                                          float* __restrict__ C,
                                          const float* __restrict__ R,
                                          int mode, int bN, int bM) {
    extern __shared__ char smem[];
    const uint32_t TILES = smem_u32(smem);
    const int tid = threadIdx.x;
    const int wid = tid >> 5;
    const int lid = tid & 31;

    const int warp_m = (wid >> 2) * 64;
    const int warp_n = (wid & 3) * 32;

    const int lrow = lid & 7;
    const int g    = lid >> 3;

    const float* Abase = A  + (size_t)bM * 128 * E_C;
    const float* Bbase = Bt + (size_t)bN * 128 * E_C;

    float acc[4][4][4];
    #pragma unroll
    for (int mb = 0; mb < 4; mb++)
        #pragma unroll
        for (int nb = 0; nb < 4; nb++)
            #pragma unroll
            for (int q = 0; q < 4; q++) acc[mb][nb][q] = 0.f;

    #pragma unroll
    for (int s = 0; s < GSTAGES - 1; s++)
        gemm_load_stage(Abase, Bbase, TILES + (uint32_t)s * 32768u, s * 32, tid);

    for (int kt = 0; kt < GNITER; kt++) {
        if (kt >= GNITER - 1)
            asm volatile("cp.async.wait_group 0;" ::: "memory");
        else
            asm volatile("cp.async.wait_group 1;" ::: "memory");
        __syncthreads();

        const uint32_t sA = TILES + (uint32_t)(kt % GSTAGES) * 32768u;
        const uint32_t sB = sA + 16384u;

        #pragma unroll
        for (int ks = 0; ks < 4; ks++) {
            uint32_t af[4][4];
            #pragma unroll
            for (int mb = 0; mb < 4; mb++) {
                int row   = warp_m + mb * 16 + lrow + (g & 1) * 8;
                int chunk = ks * 2 + (g >> 1);
                ldsm4(af[mb], sA + SWZ((uint32_t)(row * 128 + chunk * 16)));
            }
            uint32_t bf[2][4];
            #pragma unroll
            for (int nb2 = 0; nb2 < 2; nb2++) {
                int nrow  = warp_n + nb2 * 16 + lrow + (g >> 1) * 8;
                int chunk = ks * 2 + (g & 1);
                ldsm4(bf[nb2], sB + SWZ((uint32_t)(nrow * 128 + chunk * 16)));
            }
            #pragma unroll
            for (int mb = 0; mb < 4; mb++)
                #pragma unroll
                for (int nb = 0; nb < 4; nb++)
                    mma_tf32(acc[mb][nb], af[mb],
                             bf[nb >> 1][(nb & 1) * 2], bf[nb >> 1][(nb & 1) * 2 + 1]);
        }

        if (kt + GSTAGES - 1 < GNITER) {
            __syncthreads();
            gemm_load_stage(Abase, Bbase,
                            TILES + (uint32_t)((kt + GSTAGES - 1) % GSTAGES) * 32768u,
                            (kt + GSTAGES - 1) * 32, tid);
        }
    }

    #pragma unroll
    for (int mb = 0; mb < 4; mb++) {
        #pragma unroll
        for (int nb = 0; nb < 4; nb++) {
            const int row0 = bM * 128 + warp_m + mb * 16 + (lid >> 2);
            const int col  = bN * 128 + warp_n + nb * 8 + 2 * (lid & 3);
            #pragma unroll
            for (int h = 0; h < 2; h++) {
                float2 v;
                v.x = acc[mb][nb][h * 2 + 0];
                v.y = acc[mb][nb][h * 2 + 1];
                const size_t idx = (size_t)(row0 + h * 8) * E_C + col;
                if (mode == 1) {
                    v.x = 1.f / (1.f + __expf(-v.x));
                    v.y = 1.f / (1.f + __expf(-v.y));
                } else if (mode == 2) {
                    float2 r2 = *reinterpret_cast<const float2*>(R + idx);
                    v.x += r2.x; v.y += r2.y;
                }
                *reinterpret_cast<float2*>(C + idx) = v;
            }
        }
    }
}

// merged k/v/r GEMM: blockIdx.z selects slice; z==2 applies sigmoid
__global__ __launch_bounds__(256, 2)
void gemm_kvr_kernel() {
    const int z = blockIdx.z;
    gemm_body(g_mix[z], g_bt + (size_t)z * E_C * E_C, g_kvr[z], nullptr,
              (z == 2) ? 1 : 0, blockIdx.x, blockIdx.y);
}

// final GEMM: out = x + rwkv @ Wo
__global__ __launch_bounds__(256, 2)
void gemm_out_kernel(float* __restrict__ C, const float* __restrict__ R) {
    gemm_body(g_rwkv, g_bt + 3 * (size_t)E_C * E_C, C, R, 2, blockIdx.x, blockIdx.y);
}

// ---------------- Phase A: per-segment zero-init summaries ------------------
// manual 2-stage pipeline with NAMED buffers (all register-resident)
__global__ __launch_bounds__(256)
void scanA_kernel(const float* __restrict__ td_in) {
    const int e = blockIdx.x * blockDim.x + threadIdx.x;
    const int s = blockIdx.y;
    const float dec = -__expf(td_in[e]);

    float aa = 0.f, bb = 0.f, pp = -1e30f;
    const float* kp = &g_kvr[0][(size_t)s * SEGL * E_C + e];
    const float* vp = &g_kvr[1][(size_t)s * SEGL * E_C + e];
    constexpr int NC = SEGL / 8;     // 8 chunks

    float ka[8], va[8], kb[8], vb[8];
    #pragma unroll
    for (int u = 0; u < 8; u++) {
        ka[u] = kp[(size_t)u * E_C];
        va[u] = vp[(size_t)u * E_C];
    }

    #pragma unroll 1
    for (int c = 0; c < NC; c += 2) {
        const size_t b1 = (size_t)(c + 1) * 8 * E_C;
        #pragma unroll
        for (int u = 0; u < 8; u++) {
            kb[u] = kp[b1 + (size_t)u * E_C];
            vb[u] = vp[b1 + (size_t)u * E_C];
        }
        #pragma unroll
        for (int u = 0; u < 8; u++) wkv_update(ka[u], va[u], dec, aa, bb, pp);
        if (c + 2 < NC) {
            const size_t b2 = (size_t)(c + 2) * 8 * E_C;
            #pragma unroll
            for (int u = 0; u < 8; u++) {
                ka[u] = kp[b2 + (size_t)u * E_C];
                va[u] = vp[b2 + (size_t)u * E_C];
            }
        }
        #pragma unroll
        for (int u = 0; u < 8; u++) wkv_update(kb[u], vb[u], dec, aa, bb, pp);
    }
    g_ua[s * E_C + e] = aa;
    g_ub[s * E_C + e] = bb;
    g_up[s * E_C + e] = pp;
}

// ---------------- Phase B: compose summaries (pipelined, named buffers) ------
__global__ void scanB_kernel(const float* __restrict__ aa_in,
                             const float* __restrict__ bb_in,
                             const float* __restrict__ pp_in,
                             const float* __restrict__ td_in,
                             const float* __restrict__ x,
                             float* __restrict__ out_tail,
                             int write_tail) {
    const int e = blockIdx.x * blockDim.x + threadIdx.x;
    if (e >= E_C) return;

    float aa = aa_in[e], bb = bb_in[e], pp = pp_in[e];
    const float Ld = (float)SEGL * (-__expf(td_in[e]));
    constexpr int NB = SEG / 8;      // 16 batches

    float ua0[8], ub0[8], up0[8], ua1[8], ub1[8], up1[8];
    #pragma unroll
    for (int u = 0; u < 8; u++) {
        ua0[u] = g_ua[u * E_C + e];
        ub0[u] = g_ub[u * E_C + e];
        up0[u] = g_up[u * E_C + e];
    }

    #pragma unroll 1
    for (int c = 0; c < NB; c += 2) {
        const int b1 = (c + 1) * 8;
        #pragma unroll
        for (int u = 0; u < 8; u++) {
            ua1[u] = g_ua[(b1 + u) * E_C + e];
            ub1[u] = g_ub[(b1 + u) * E_C + e];
            up1[u] = g_up[(b1 + u) * E_C + e];
        }
        #pragma unroll
        for (int u = 0; u < 8; u++) {
            const int s = c * 8 + u;
            g_sa[s * E_C + e] = aa;
            g_sb[s * E_C + e] = bb;
            g_sp[s * E_C + e] = pp;
            const float q  = pp + Ld;
            const float pn = fmaxf(q, up0[u]);
            const float eq = __expf(q - pn);
            const float eu = __expf(up0[u] - pn);
            aa = aa * eq + ua0[u] * eu;
            bb = bb * eq + ub0[u] * eu;
            pp = pn;
        }
        if (c + 2 < NB) {
            const int b2 = (c + 2) * 8;
            #pragma unroll
            for (int u = 0; u < 8; u++) {
                ua0[u] = g_ua[(b2 + u) * E_C + e];
                ub0[u] = g_ub[(b2 + u) * E_C + e];
                up0[u] = g_up[(b2 + u) * E_C + e];
            }
        }
        #pragma unroll
        for (int u = 0; u < 8; u++) {
            const int s = (c + 1) * 8 + u;
            g_sa[s * E_C + e] = aa;
            g_sb[s * E_C + e] = bb;
            g_sp[s * E_C + e] = pp;
            const float q  = pp + Ld;
            const float pn = fmaxf(q, up1[u]);
            const float eq = __expf(q - pn);
            const float eu = __expf(up1[u] - pn);
            aa = aa * eq + ua1[u] * eu;
            bb = bb * eq + ub1[u] * eu;
            pp = pn;
        }
    }

    if (write_tail) {
        out_tail[(size_t)T_C * E_C + 0 * E_C + e] = x[(size_t)(T_C - 1) * E_C + e];
        out_tail[(size_t)T_C * E_C + 1 * E_C + e] = aa;
        out_tail[(size_t)T_C * E_C + 2 * E_C + e] = bb;
        out_tail[(size_t)T_C * E_C + 3 * E_C + e] = pp;
    }
}

// ---------------- Phase C: replay segments (pipelined, named buffers) --------
__global__ __launch_bounds__(256)
void scanC_kernel(const float* __restrict__ tf_in,
                  const float* __restrict__ td_in) {
    const int e = blockIdx.x * blockDim.x + threadIdx.x;
    const int s = blockIdx.y;
    const float tf  = tf_in[e];
    const float dec = -__expf(td_in[e]);

    float aa = g_sa[s * E_C + e];
    float bb = g_sb[s * E_C + e];
    float pp = g_sp[s * E_C + e];
    const size_t base = (size_t)s * SEGL * E_C + e;
    const float* kp = &g_kvr[0][base];
    const float* vp = &g_kvr[1][base];
    const float* rp = &g_kvr[2][base];
    float* op = &g_rwkv[base];
    constexpr int NC = SEGL / 8;     // 8 chunks

    float ka[8], va[8], ra[8], kb[8], vb[8], rb[8];
    #pragma unroll
    for (int u = 0; u < 8; u++) {
        ka[u] = kp[(size_t)u * E_C];
        va[u] = vp[(size_t)u * E_C];
        ra[u] = rp[(size_t)u * E_C];
    }

    #pragma unroll 1
    for (int c = 0; c < NC; c += 2) {
        const size_t b1 = (size_t)(c + 1) * 8 * E_C;
        #pragma unroll
        for (int u = 0; u < 8; u++) {
            kb[u] = kp[b1 + (size_t)u * E_C];
            vb[u] = vp[b1 + (size_t)u * E_C];
            rb[u] = rp[b1 + (size_t)u * E_C];
        }
        {
            const size_t ob = (size_t)c * 8 * E_C;
            #pragma unroll
            for (int u = 0; u < 8; u++) {
                op[ob + (size_t)u * E_C] = wkv_out(ka[u], va[u], ra[u], tf, aa, bb, pp);
                wkv_update(ka[u], va[u], dec, aa, bb, pp);
            }
        }
        if (c + 2 < NC) {
            const size_t b2 = (size_t)(c + 2) * 8 * E_C;
            #pragma unroll
            for (int u = 0; u < 8; u++) {
                ka[u] = kp[b2 + (size_t)u * E_C];
                va[u] = vp[b2 + (size_t)u * E_C];
                ra[u] = rp[b2 + (size_t)u * E_C];
            }
        }
        {
            const size_t ob = (size_t)(c + 1) * 8 * E_C;
            #pragma unroll
            for (int u = 0; u < 8; u++) {
                op[ob + (size_t)u * E_C] = wkv_out(kb[u], vb[u], rb[u], tf, aa, bb, pp);
                wkv_update(kb[u], vb[u], dec, aa, bb, pp);
            }
        }
    }
}

// ---------------- launch -----------------------------------------------------
extern "C" void kernel_launch(void* const* d_in, const int* in_sizes, int n_in,
                              void* d_out, int out_size) {
    const float* x   = (const float*)d_in[0];
    const float* sx  = (const float*)d_in[1];
    const float* aa  = (const float*)d_in[2];
    const float* bb  = (const float*)d_in[3];
    const float* pp  = (const float*)d_in[4];
    const float* tf  = (const float*)d_in[5];
    const float* td  = (const float*)d_in[6];
    const float* tmk = (const float*)d_in[7];
    const float* tmv = (const float*)d_in[8];
    const float* tmr = (const float*)d_in[9];
    const float* Wk  = (const float*)d_in[10];
    const float* Wv  = (const float*)d_in[11];
    const float* Wr  = (const float*)d_in[12];
    const float* Wo  = (const float*)d_in[13];
    float* out = (float*)d_out;

    cudaFuncSetAttribute(gemm_kvr_kernel,
                         cudaFuncAttributeMaxDynamicSharedMemorySize, GSMEM_BYTES);
    cudaFuncSetAttribute(gemm_out_kernel,
                         cudaFuncAttributeMaxDynamicSharedMemorySize, GSMEM_BYTES);

    // 1) token-shift mixes (tf32-rounded)
    {
        const int n4 = T_C * E_C / 4;
        mix_kernel<<<(n4 + 255) / 256, 256>>>(x, sx, tmk, tmv, tmr);
    }

    // 2) weight transposes -> [N,K] K-major, tf32-rounded
    transpose_kernel<<<dim3(32, 32, 4), dim3(32, 8)>>>(Wk, Wv, Wr, Wo);

    // 3) merged k, v, r GEMMs (HMMA tf32)
    gemm_kvr_kernel<<<dim3(E_C / 128, T_C / 128, 3), 256, GSMEM_BYTES>>>();

    // 4) segment-parallel WKV scan
    const int write_tail = (out_size >= T_C * E_C + 4 * E_C) ? 1 : 0;
    dim3 sgrid(E_C / 256, SEG);
    scanA_kernel<<<sgrid, 256>>>(td);
    scanB_kernel<<<4, 256>>>(aa, bb, pp, td, x, out, write_tail);
    scanC_kernel<<<sgrid, 256>>>(tf, td);

    // 5) out = x + rwkv @ Wo
    gemm_out_kernel<<<dim3(E_C / 128, T_C / 128), 256, GSMEM_BYTES>>>(out, x);
}